// round 16
// baseline (speedup 1.0000x reference)
#include <cuda_runtime.h>

// CausalConv1d (depthwise, K=4) + SiLU — FINAL (converged; R1-R14 bracketing).
// x: (B=4, S=8192, D=2048) fp32, w: (D, 1, 4) fp32, out: (B, S, D) fp32
// y[b,s,d] = silu( sum_{k=0..3} x[b, s-3+k, d] * w[d,0,k] )   (causal left zero-pad)
//
// Every design element validated by a measured bracketing experiment:
//  - T=8 outputs/thread, one float4 channel-group/thread: 11 front-batched
//    independent LDG.128 (high MLP_p1) -> fully unrolled FMA + SiLU epilogue.
//    (chunked sliding window +8%; T=16 +1.5%; halo-split load policy +2%;
//     s-fastest launch order neutral; 256-thread CTAs neutral)
//  - x reads evict-first (__ldcs); stores evict-first (__stcs) — preserves L2
//    dirty-line write coalescing (write-through stores +8%).
//  - SiLU via tanh.approx: silu(v) = h + h*tanh(h), h=v/2 — one MUFU op.
//  - 128 threads/CTA, 7 CTAs/SM, 72 regs (8 CTAs/SM and 256-wide both neutral:
//    not warp-limited at 28 warps).
//
// Measured (6 replications): 81.3-82.1us bench / 74.8-75.6us kernel.
// App rate 7.2 TB/s = 90% of spec HBM, DRAM pipe ~81%, L2 under the LTS cap —
// at the mixed read/write HBM turnaround ceiling; DRAM rate invariant across
// occupancy, tiling, CTA-width, cache-policy, and launch-order axes.

constexpr int B_ = 4;
constexpr int S_ = 8192;
constexpr int D_ = 2048;
constexpr int D4 = D_ / 4;      // 512 float4 lanes along channel dim
constexpr int T_ = 8;           // s-positions per thread
constexpr int THREADS = 128;

__device__ __forceinline__ float silu_f(float v) {
    float h = 0.5f * v;
    float t;
    asm("tanh.approx.f32 %0, %1;" : "=f"(t) : "f"(h));
    return fmaf(h, t, h);
}

__global__ __launch_bounds__(THREADS, 7)
void causal_conv1d_silu_kernel(const float4* __restrict__ x,
                               const float4* __restrict__ w4,   // [D] float4: 4 taps / channel
                               float4* __restrict__ y)
{
    const int d4 = blockIdx.x * THREADS + threadIdx.x;   // float4 channel group
    const int s0 = blockIdx.y * T_;
    const int b  = blockIdx.z;

    const float4* xb = x + ((b * S_ + s0) * D4 + d4);
    float4*       yb = y + ((b * S_ + s0) * D4 + d4);

    // ---- Front-batched loads: 11 independent LDG.128, evict-first ----
    float4 r[T_ + 3];
    if (blockIdx.y != 0) {
        r[0] = __ldcs(xb - 3 * D4);
        r[1] = __ldcs(xb - 2 * D4);
        r[2] = __ldcs(xb - 1 * D4);
    } else {
        const float4 z = make_float4(0.f, 0.f, 0.f, 0.f);
        r[0] = z; r[1] = z; r[2] = z;
    }
#pragma unroll
    for (int t = 0; t < T_; ++t)
        r[t + 3] = __ldcs(xb + t * D4);

    // Taps: w4[c] = (k0,k1,k2,k3) of channel c (32 KB total, L2-resident).
    const float4* wb = w4 + d4 * 4;
    const float4 wA = __ldg(wb + 0);
    const float4 wB = __ldg(wb + 1);
    const float4 wC = __ldg(wb + 2);
    const float4 wD = __ldg(wb + 3);

#pragma unroll
    for (int t = 0; t < T_; ++t) {
        float ox = fmaf(r[t].x, wA.x, fmaf(r[t+1].x, wA.y, fmaf(r[t+2].x, wA.z, r[t+3].x * wA.w)));
        float oy = fmaf(r[t].y, wB.x, fmaf(r[t+1].y, wB.y, fmaf(r[t+2].y, wB.z, r[t+3].y * wB.w)));
        float oz = fmaf(r[t].z, wC.x, fmaf(r[t+1].z, wC.y, fmaf(r[t+2].z, wC.z, r[t+3].z * wC.w)));
        float ow = fmaf(r[t].w, wD.x, fmaf(r[t+1].w, wD.y, fmaf(r[t+2].w, wD.z, r[t+3].w * wD.w)));

        float4 o;
        o.x = silu_f(ox);
        o.y = silu_f(oy);
        o.z = silu_f(oz);
        o.w = silu_f(ow);

        // Streaming store: output never re-read; L2 coalesces dirty lines.
        __stcs(yb + t * D4, o);
    }
}

extern "C" void kernel_launch(void* const* d_in, const int* in_sizes, int n_in,
                              void* d_out, int out_size)
{
    const float4* x  = (const float4*)d_in[0];
    const float4* w4 = (const float4*)d_in[1];
    float4* y = (float4*)d_out;

    dim3 block(THREADS, 1, 1);
    dim3 grid(D4 / THREADS, S_ / T_, B_);   // (4, 1024, 4) = 16384 CTAs
    causal_conv1d_silu_kernel<<<grid, block>>>(x, w4, y);
}

// round 17
// speedup vs baseline: 1.0182x; 1.0182x over previous
#include <cuda_runtime.h>

// CausalConv1d (depthwise, K=4) + SiLU — FINAL (converged; R1-R15 bracketing).
// x: (B=4, S=8192, D=2048) fp32, w: (D, 1, 4) fp32, out: (B, S, D) fp32
// y[b,s,d] = silu( sum_{k=0..3} x[b, s-3+k, d] * w[d,0,k] )   (causal left zero-pad)
//
// Every design element validated by a measured bracketing experiment:
//  - T=8 outputs/thread, one float4 channel-group/thread: 11 front-batched
//    independent LDG.128 (high MLP_p1) -> fully unrolled FMA + SiLU epilogue.
//    (chunked sliding window +8%; T=16 +1.5%; halo-split load policy +2%;
//     s-fastest launch order neutral; 256-thread CTAs neutral)
//  - x reads evict-first (__ldcs); stores evict-first (__stcs) — preserves L2
//    dirty-line write coalescing (write-through stores +8%).
//  - SiLU via tanh.approx: silu(v) = h + h*tanh(h), h=v/2 — one MUFU op.
//  - 128 threads/CTA, 7 CTAs/SM, 72 regs (8 CTAs/SM and 256-wide both
//    neutral: not warp-limited at 28 warps).
//
// Measured (7 replications): 81.3-82.2us bench / 74.8-75.6us kernel.
// App rate 7.2 TB/s = 90% of spec HBM, DRAM pipe ~81%, L2 under the LTS cap —
// at the mixed read/write HBM turnaround ceiling; DRAM rate invariant across
// occupancy, tiling, CTA-width, cache-policy, and launch-order axes.

constexpr int B_ = 4;
constexpr int S_ = 8192;
constexpr int D_ = 2048;
constexpr int D4 = D_ / 4;      // 512 float4 lanes along channel dim
constexpr int T_ = 8;           // s-positions per thread
constexpr int THREADS = 128;

__device__ __forceinline__ float silu_f(float v) {
    float h = 0.5f * v;
    float t;
    asm("tanh.approx.f32 %0, %1;" : "=f"(t) : "f"(h));
    return fmaf(h, t, h);
}

__global__ __launch_bounds__(THREADS, 7)
void causal_conv1d_silu_kernel(const float4* __restrict__ x,
                               const float4* __restrict__ w4,   // [D] float4: 4 taps / channel
                               float4* __restrict__ y)
{
    const int d4 = blockIdx.x * THREADS + threadIdx.x;   // float4 channel group
    const int s0 = blockIdx.y * T_;
    const int b  = blockIdx.z;

    const float4* xb = x + ((b * S_ + s0) * D4 + d4);
    float4*       yb = y + ((b * S_ + s0) * D4 + d4);

    // ---- Front-batched loads: 11 independent LDG.128, evict-first ----
    float4 r[T_ + 3];
    if (blockIdx.y != 0) {
        r[0] = __ldcs(xb - 3 * D4);
        r[1] = __ldcs(xb - 2 * D4);
        r[2] = __ldcs(xb - 1 * D4);
    } else {
        const float4 z = make_float4(0.f, 0.f, 0.f, 0.f);
        r[0] = z; r[1] = z; r[2] = z;
    }
#pragma unroll
    for (int t = 0; t < T_; ++t)
        r[t + 3] = __ldcs(xb + t * D4);

    // Taps: w4[c] = (k0,k1,k2,k3) of channel c (32 KB total, L2-resident).
    const float4* wb = w4 + d4 * 4;
    const float4 wA = __ldg(wb + 0);
    const float4 wB = __ldg(wb + 1);
    const float4 wC = __ldg(wb + 2);
    const float4 wD = __ldg(wb + 3);

#pragma unroll
    for (int t = 0; t < T_; ++t) {
        float ox = fmaf(r[t].x, wA.x, fmaf(r[t+1].x, wA.y, fmaf(r[t+2].x, wA.z, r[t+3].x * wA.w)));
        float oy = fmaf(r[t].y, wB.x, fmaf(r[t+1].y, wB.y, fmaf(r[t+2].y, wB.z, r[t+3].y * wB.w)));
        float oz = fmaf(r[t].z, wC.x, fmaf(r[t+1].z, wC.y, fmaf(r[t+2].z, wC.z, r[t+3].z * wC.w)));
        float ow = fmaf(r[t].w, wD.x, fmaf(r[t+1].w, wD.y, fmaf(r[t+2].w, wD.z, r[t+3].w * wD.w)));

        float4 o;
        o.x = silu_f(ox);
        o.y = silu_f(oy);
        o.z = silu_f(oz);
        o.w = silu_f(ow);

        // Streaming store: output never re-read; L2 coalesces dirty lines.
        __stcs(yb + t * D4, o);
    }
}

extern "C" void kernel_launch(void* const* d_in, const int* in_sizes, int n_in,
                              void* d_out, int out_size)
{
    const float4* x  = (const float4*)d_in[0];
    const float4* w4 = (const float4*)d_in[1];
    float4* y = (float4*)d_out;

    dim3 block(THREADS, 1, 1);
    dim3 grid(D4 / THREADS, S_ / T_, B_);   // (4, 1024, 4) = 16384 CTAs
    causal_conv1d_silu_kernel<<<grid, block>>>(x, w4, y);
}